// round 5
// baseline (speedup 1.0000x reference)
#include <cuda_runtime.h>
#include <math.h>

typedef unsigned long long ull;

#define NE 80000          // B*N electrons
#define TT 2000
#define SS 12
#define HH 128
#define EB 256            // electrons per CTA
#define MASK_COEF 1.2615662610f   // GAUSS_NORM / sqrt(0.1)

// ---- f32x2 packed math (sm_103a) ----
__device__ __forceinline__ ull fma2(ull a, ull b, ull c) {
    ull d;
    asm("fma.rn.f32x2 %0, %1, %2, %3;" : "=l"(d) : "l"(a), "l"(b), "l"(c));
    return d;
}
__device__ __forceinline__ ull pack2(float lo, float hi) {
    ull d;
    asm("mov.b64 %0, {%1, %2};" : "=l"(d) : "f"(lo), "f"(hi));
    return d;
}
__device__ __forceinline__ float2 unpack2(ull v) {
    float2 r;
    asm("mov.b64 {%0, %1}, %2;" : "=f"(r.x), "=f"(r.y) : "l"(v));
    return r;
}

__global__ void zero_kernel(float* __restrict__ out, int n) {
    int i = blockIdx.x * blockDim.x + threadIdx.x;
    if (i < n) out[i] = 0.0f;
}

// smem layout (floats)
#define SM_W2   0                       // 128*128 = 16384
#define SM_H1   (SM_W2 + HH*HH)         // 128 rows(k) x 256 e = 32768
#define SM_W1   (SM_H1 + HH*EB)         // 384
#define SM_B1   (SM_W1 + 3*HH)          // 128
#define SM_B2   (SM_B1 + HH)            // 128
#define SM_B3   (SM_B2 + HH)            // 16 (12 + pad, keeps W3 8B-aligned)
#define SM_W3   (SM_B3 + 16)            // 128*12 = 1536
#define SM_RESP (SM_W3 + HH*SS)         // 256*12 = 3072
#define SM_TOT  (SM_RESP + EB*SS)       // 54416 floats = 217664 B

__global__ __launch_bounds__(256, 1)
void fused_sensor_kernel(
    const float* __restrict__ de,    // (B,N,3)
    const float* __restrict__ mask,  // (B,N)
    const float* __restrict__ W1,    // (3,H)
    const float* __restrict__ b1,    // (H)
    const float* __restrict__ W2,    // (H,H)
    const float* __restrict__ b2,    // (H)
    const float* __restrict__ W3,    // (H,S)
    const float* __restrict__ b3,    // (S)
    float* __restrict__ out)         // (B,S,T)
{
    extern __shared__ float sm[];
    const int tid = threadIdx.x;

    // ---- stage weights into smem ----
    {
        const float4* src = (const float4*)W2;
        float4* dst = (float4*)(sm + SM_W2);
        for (int i = tid; i < HH * HH / 4; i += 256) dst[i] = src[i];
    }
    for (int i = tid; i < 3 * HH; i += 256) sm[SM_W1 + i] = W1[i];
    if (tid < HH) { sm[SM_B1 + tid] = b1[tid]; sm[SM_B2 + tid] = b2[tid]; }
    for (int i = tid; i < HH * SS; i += 256) sm[SM_W3 + i] = W3[i];
    if (tid < SS) sm[SM_B3 + tid] = b3[tid];

    // ---- per-thread electron inputs (thread = local e for layer1/scatter) ----
    const int eg = blockIdx.x * EB + tid;
    float x0 = 0.f, x1 = 0.f, x2 = 0.f, msk = 0.f;
    if (eg < NE) {
        x0 = de[3 * eg + 0];
        x1 = de[3 * eg + 1];
        x2 = de[3 * eg + 2];
        msk = mask[eg];
    }
    __syncthreads();

    // ---- layer 1: h1s[k][e] (k-major, 256 f32 rows) ----
#pragma unroll 4
    for (int k = 0; k < HH; ++k) {
        float v = fmaf(x0, sm[SM_W1 + k], sm[SM_B1 + k]);
        v = fmaf(x1, sm[SM_W1 + HH + k], v);
        v = fmaf(x2, sm[SM_W1 + 2 * HH + k], v);
        sm[SM_H1 + k * EB + tid] = fmaxf(v, 0.0f);
    }
    __syncthreads();

    // ---- layer 2 GEMM: tile 16e x 8j per thread, e-pairs packed in f32x2 ----
    const int tx = tid >> 4;            // e-block: e0 = tx*16
    const int ty = tid & 15;            // j-block: j0 = ty*8  (warp spans all 16 ty)
    const int e0 = tx * 16;
    const int j0 = ty * 8;

    ull acc[8][8];                      // [j][e-pair]
#pragma unroll
    for (int j = 0; j < 8; ++j)
#pragma unroll
        for (int p = 0; p < 8; ++p) acc[j][p] = 0ULL;

    const ull* abase = (const ull*)(sm + SM_H1) + tx * 8;   // row stride 128 ull
    const float* bbase = sm + SM_W2 + j0;

    for (int k = 0; k < HH; ++k) {
        const ull* ar = abase + k * (EB / 2);
        ulonglong2 A0 = *(const ulonglong2*)(ar + 0);
        ulonglong2 A1 = *(const ulonglong2*)(ar + 2);
        ulonglong2 A2 = *(const ulonglong2*)(ar + 4);
        ulonglong2 A3 = *(const ulonglong2*)(ar + 6);
        const float* br = bbase + k * HH;
        float4 B0 = *(const float4*)(br);
        float4 B1 = *(const float4*)(br + 4);

        ull a[8] = {A0.x, A0.y, A1.x, A1.y, A2.x, A2.y, A3.x, A3.y};
        ull bd[8];
        bd[0] = pack2(B0.x, B0.x); bd[1] = pack2(B0.y, B0.y);
        bd[2] = pack2(B0.z, B0.z); bd[3] = pack2(B0.w, B0.w);
        bd[4] = pack2(B1.x, B1.x); bd[5] = pack2(B1.y, B1.y);
        bd[6] = pack2(B1.z, B1.z); bd[7] = pack2(B1.w, B1.w);

#pragma unroll
        for (int j = 0; j < 8; ++j)
#pragma unroll
            for (int p = 0; p < 8; ++p)
                acc[j][p] = fma2(a[p], bd[j], acc[j][p]);
    }

    // ---- epilogue: relu + layer 3 + butterfly reduce over ty (lane bits 0..3) ----
#pragma unroll 1
    for (int i = 0; i < 16; ++i) {
        const int p = i >> 1;
        ull accS[6];
#pragma unroll
        for (int sp = 0; sp < 6; ++sp) accS[sp] = 0ULL;
#pragma unroll
        for (int j = 0; j < 8; ++j) {
            float2 hv = unpack2(acc[j][p]);
            float h2 = (i & 1) ? hv.y : hv.x;
            h2 = fmaxf(h2 + sm[SM_B2 + j0 + j], 0.0f);
            ull hd = pack2(h2, h2);
            const ull* w3r = (const ull*)(sm + SM_W3 + (j0 + j) * SS);
#pragma unroll
            for (int sp = 0; sp < 6; ++sp)
                accS[sp] = fma2(hd, w3r[sp], accS[sp]);
        }
        float r[12];
#pragma unroll
        for (int sp = 0; sp < 6; ++sp) {
            float2 v = unpack2(accS[sp]);
            r[2 * sp] = v.x; r[2 * sp + 1] = v.y;
        }
#pragma unroll
        for (int m = 1; m <= 8; m <<= 1)
#pragma unroll
            for (int s = 0; s < 12; ++s)
                r[s] += __shfl_xor_sync(0xffffffffu, r[s], m);
        if (ty == 0) {
            const int e = e0 + i;
#pragma unroll
            for (int s = 0; s < 12; ++s) sm[SM_RESP + e * SS + s] = r[s];
        }
    }
    __syncthreads();

    // ---- sparse Gaussian scatter (thread = local e again) ----
    if (eg < NE) {
        float resp[12];
#pragma unroll
        for (int s = 0; s < 12; ++s)
            resp[s] = sm[SM_RESP + tid * SS + s] + sm[SM_B3 + s];

        const float z = x2;
        const float c = msk * MASK_COEF;
        int t0 = (int)ceilf(z - 3.0f);
        int t1 = (int)floorf(z + 3.0f);
        if (t0 < 0) t0 = 0;
        if (t1 > TT - 1) t1 = TT - 1;
        const int b = eg / 10000;
        float* ob = out + (size_t)b * SS * TT;

        for (int t = t0; t <= t1; ++t) {
            float d = (float)t - z;
            float w = __expf(-5.0f * d * d) * c;
#pragma unroll
            for (int s = 0; s < 12; ++s)
                atomicAdd(&ob[s * TT + t], w * resp[s]);
        }
    }
}

extern "C" void kernel_launch(void* const* d_in, const int* in_sizes, int n_in,
                              void* d_out, int out_size) {
    const float* de   = (const float*)d_in[0];
    const float* mask = (const float*)d_in[1];
    const float* W1   = (const float*)d_in[2];
    const float* b1   = (const float*)d_in[3];
    const float* W2   = (const float*)d_in[4];
    const float* b2   = (const float*)d_in[5];
    const float* W3   = (const float*)d_in[6];
    const float* b3   = (const float*)d_in[7];
    float* out = (float*)d_out;

    const int total_out = 8 * SS * TT;  // 192000
    zero_kernel<<<(total_out + 255) / 256, 256>>>(out, total_out);

    const int smem_bytes = SM_TOT * (int)sizeof(float);  // 217664
    cudaFuncSetAttribute(fused_sensor_kernel,
                         cudaFuncAttributeMaxDynamicSharedMemorySize, smem_bytes);

    const int blocks = (NE + EB - 1) / EB;  // 313
    fused_sensor_kernel<<<blocks, 256, smem_bytes>>>(
        de, mask, W1, b1, W2, b2, W3, b3, out);
}

// round 7
// speedup vs baseline: 4.0410x; 4.0410x over previous
#include <cuda_runtime.h>
#include <cuda_bf16.h>
#include <math.h>
#include <stdint.h>

typedef unsigned long long ull;

#define NE 80000
#define TT 2000
#define SS 12
#define HH 128
#define EB 128                     // electrons per CTA (MMA M)
#define MASK_COEF 1.2615662610f    // GAUSS_NORM / sqrt(0.1)

// smem word (f32/u32) offsets
#define SW_AHI 0                   // 128 rows x 68 words (bf16x2 k-pairs, padded)
#define SW_ALO (SW_AHI + 128*68)   // 8704
#define SW_BHI (SW_ALO + 128*68)   // 17408: 64 kp x 136 words
#define SW_BLO (SW_BHI + 64*136)   // 26112
#define SW_TOT (SW_BLO + 64*136)   // 34816 words = 139264 B
#define SW_H2  0                   // h2[128][130] f32, reuses A region (16640 <= 17408)
#define H2_STRIDE 130

__device__ __forceinline__ ull fma2(ull a, ull b, ull c) {
    ull d; asm("fma.rn.f32x2 %0, %1, %2, %3;" : "=l"(d) : "l"(a), "l"(b), "l"(c)); return d;
}
__device__ __forceinline__ ull pack2(float lo, float hi) {
    ull d; asm("mov.b64 %0, {%1, %2};" : "=l"(d) : "f"(lo), "f"(hi)); return d;
}
__device__ __forceinline__ float2 unpack2(ull v) {
    float2 r; asm("mov.b64 {%0, %1}, %2;" : "=f"(r.x), "=f"(r.y) : "l"(v)); return r;
}
__device__ __forceinline__ uint32_t bfpack(float a, float b) {
    __nv_bfloat162 t(__float2bfloat16(a), __float2bfloat16(b));  // .x = low half
    return *(uint32_t*)&t;
}
__device__ __forceinline__ void mma16816(float* c, const uint32_t* a, const uint32_t* b) {
    asm volatile(
        "mma.sync.aligned.m16n8k16.row.col.f32.bf16.bf16.f32 "
        "{%0,%1,%2,%3}, {%4,%5,%6,%7}, {%8,%9}, {%0,%1,%2,%3};"
        : "+f"(c[0]), "+f"(c[1]), "+f"(c[2]), "+f"(c[3])
        : "r"(a[0]), "r"(a[1]), "r"(a[2]), "r"(a[3]), "r"(b[0]), "r"(b[1]));
}

__global__ void zero_kernel(float* __restrict__ out, int n) {
    int i = blockIdx.x * blockDim.x + threadIdx.x;
    if (i < n) out[i] = 0.0f;
}

__global__ __launch_bounds__(256, 1)
void fused_sensor_kernel(
    const float* __restrict__ de,    // (B,N,3)
    const float* __restrict__ mask,  // (B,N)
    const float* __restrict__ W1,    // (3,H)
    const float* __restrict__ b1,    // (H)
    const float* __restrict__ W2,    // (H,H)
    const float* __restrict__ b2,    // (H)
    const float* __restrict__ W3,    // (H,S)
    const float* __restrict__ b3,    // (S)
    float* __restrict__ out)         // (B,S,T)
{
    extern __shared__ uint32_t smw[];
    const int tid  = threadIdx.x;
    const int lane = tid & 31;
    const int wid  = tid >> 5;

    // ---------- stage B = W2 (K x N, k-major) as split bf16x2 k-pairs ----------
    // Bpack[kp][n] = bf16x2(W2[2kp][n], W2[2kp+1][n]); row stride 136 words.
#pragma unroll 4
    for (int i = 0; i < 32; ++i) {
        int idx = tid + i * 256;               // 8192 entries
        int kp = idx >> 7, n = idx & 127;
        float v0 = W2[(2 * kp) * HH + n];      // coalesced
        float v1 = W2[(2 * kp + 1) * HH + n];
        float h0 = __bfloat162float(__float2bfloat16(v0));
        float h1 = __bfloat162float(__float2bfloat16(v1));
        smw[SW_BHI + kp * 136 + n] = bfpack(v0, v1);
        smw[SW_BLO + kp * 136 + n] = bfpack(v0 - h0, v1 - h1);
    }

    // ---------- layer 1 -> Apack (2 threads per electron, 32 k-pairs each) ----------
    const int el = tid >> 1;                   // local electron 0..127
    const int q  = tid & 1;
    const int eg = blockIdx.x * EB + el;
    const float x0 = de[3 * eg + 0];
    const float x1 = de[3 * eg + 1];
    const float x2 = de[3 * eg + 2];
    const float msk = mask[eg];
#pragma unroll 4
    for (int i = 0; i < 32; ++i) {
        int kp = q * 32 + i, k = 2 * kp;
        float v0 = fmaf(x2, W1[2 * HH + k],     fmaf(x1, W1[HH + k],     fmaf(x0, W1[k],     b1[k])));
        float v1 = fmaf(x2, W1[2 * HH + k + 1], fmaf(x1, W1[HH + k + 1], fmaf(x0, W1[k + 1], b1[k + 1])));
        v0 = fmaxf(v0, 0.0f);
        v1 = fmaxf(v1, 0.0f);
        float h0 = __bfloat162float(__float2bfloat16(v0));
        float h1 = __bfloat162float(__float2bfloat16(v1));
        smw[SW_AHI + el * 68 + kp] = bfpack(v0, v1);
        smw[SW_ALO + el * 68 + kp] = bfpack(v0 - h0, v1 - h1);
    }
    __syncthreads();

    // ---------- layer-2 GEMM: warp (mw,nw) owns 32 rows x 64 cols ----------
    const int mw = wid & 3, nw = wid >> 2;
    const int m0 = mw * 32, n0 = nw * 64;
    float acc[2][8][4];
#pragma unroll
    for (int mt = 0; mt < 2; ++mt)
#pragma unroll
        for (int nt = 0; nt < 8; ++nt)
#pragma unroll
            for (int c = 0; c < 4; ++c) acc[mt][nt][c] = 0.0f;

    const int ar = m0 + (lane >> 2);           // A fragment row
    const int ac = lane & 3;                   // A k-pair sub-index
    const int bc = n0 + (lane >> 2);           // B fragment col
    // three split products: (Ahi,Bhi), (Alo,Bhi), (Ahi,Blo)
#pragma unroll 1
    for (int sp = 0; sp < 3; ++sp) {
        const uint32_t* Ap = smw + (sp == 1 ? SW_ALO : SW_AHI);
        const uint32_t* Bp = smw + (sp == 2 ? SW_BLO : SW_BHI);
#pragma unroll
        for (int kk = 0; kk < 8; ++kk) {
            const int kb = kk * 8;
            uint32_t a[2][4], b[8][2];
#pragma unroll
            for (int mt = 0; mt < 2; ++mt) {
                const uint32_t* A0 = Ap + (ar + mt * 16) * 68 + kb + ac;
                a[mt][0] = A0[0];
                a[mt][1] = A0[8 * 68];
                a[mt][2] = A0[4];
                a[mt][3] = A0[8 * 68 + 4];
            }
            const uint32_t* B0 = Bp + (kb + ac) * 136 + bc;
#pragma unroll
            for (int nt = 0; nt < 8; ++nt) {
                b[nt][0] = B0[nt * 8];
                b[nt][1] = B0[4 * 136 + nt * 8];
            }
#pragma unroll
            for (int mt = 0; mt < 2; ++mt)
#pragma unroll
                for (int nt = 0; nt < 8; ++nt)
                    mma16816(acc[mt][nt], a[mt], b[nt]);
        }
    }
    __syncthreads();   // all warps done reading A region before h2 overwrites it

    // ---------- epilogue: h2 = relu(D + b2) -> smem ----------
    {
        const int r = lane >> 2, c2 = lane & 3;
#pragma unroll
        for (int mt = 0; mt < 2; ++mt)
#pragma unroll
            for (int nt = 0; nt < 8; ++nt) {
                int j = n0 + nt * 8 + 2 * c2;
                float bj0 = b2[j], bj1 = b2[j + 1];
                int row0 = m0 + mt * 16 + r;
                float2 v0 = make_float2(fmaxf(acc[mt][nt][0] + bj0, 0.0f),
                                        fmaxf(acc[mt][nt][1] + bj1, 0.0f));
                float2 v1 = make_float2(fmaxf(acc[mt][nt][2] + bj0, 0.0f),
                                        fmaxf(acc[mt][nt][3] + bj1, 0.0f));
                *(float2*)&smw[SW_H2 + row0 * H2_STRIDE + j] = v0;
                *(float2*)&smw[SW_H2 + (row0 + 8) * H2_STRIDE + j] = v1;
            }
    }
    __syncthreads();

    // ---------- layer 3 (f32x2 over sensor pairs) + 2-lane combine ----------
    ull accS[6];
#pragma unroll
    for (int sp = 0; sp < 6; ++sp) accS[sp] = 0ULL;
    const float* h2row = (const float*)&smw[SW_H2 + el * H2_STRIDE + q * 64];
#pragma unroll 8
    for (int jj = 0; jj < 64; ++jj) {
        float h2 = h2row[jj];
        ull hd = pack2(h2, h2);
        const ull* w3r = (const ull*)(W3 + (q * 64 + jj) * SS);   // 12 f32 = 6 ull, aligned
#pragma unroll
        for (int sp = 0; sp < 6; ++sp) accS[sp] = fma2(hd, w3r[sp], accS[sp]);
    }
    float resp[SS];
#pragma unroll
    for (int sp = 0; sp < 6; ++sp) {
        float2 v = unpack2(accS[sp]);
        v.x += __shfl_xor_sync(0xffffffffu, v.x, 1);
        v.y += __shfl_xor_sync(0xffffffffu, v.y, 1);
        resp[2 * sp]     = v.x + b3[2 * sp];
        resp[2 * sp + 1] = v.y + b3[2 * sp + 1];
    }

    // ---------- sparse Gaussian scatter (exp(-5d^2) < 3e-20 beyond |d|=3) ----------
    {
        const float z = x2;
        const float c = msk * MASK_COEF;
        int t0 = (int)ceilf(z - 3.0f);
        int t1 = (int)floorf(z + 3.0f);
        if (t0 < 0) t0 = 0;
        if (t1 > TT - 1) t1 = TT - 1;
        const int b = eg / 10000;
        float* ob = out + (size_t)b * SS * TT;
        for (int t = t0 + q; t <= t1; t += 2) {
            float d = (float)t - z;
            float w = __expf(-5.0f * d * d) * c;
#pragma unroll
            for (int s = 0; s < SS; ++s)
                atomicAdd(&ob[s * TT + t], w * resp[s]);
        }
    }
}

extern "C" void kernel_launch(void* const* d_in, const int* in_sizes, int n_in,
                              void* d_out, int out_size) {
    const float* de   = (const float*)d_in[0];
    const float* mask = (const float*)d_in[1];
    const float* W1   = (const float*)d_in[2];
    const float* b1   = (const float*)d_in[3];
    const float* W2   = (const float*)d_in[4];
    const float* b2   = (const float*)d_in[5];
    const float* W3   = (const float*)d_in[6];
    const float* b3   = (const float*)d_in[7];
    float* out = (float*)d_out;

    const int total_out = 8 * SS * TT;  // 192000
    zero_kernel<<<(total_out + 255) / 256, 256>>>(out, total_out);

    const int smem_bytes = SW_TOT * 4;  // 139264
    cudaFuncSetAttribute(fused_sensor_kernel,
                         cudaFuncAttributeMaxDynamicSharedMemorySize, smem_bytes);

    fused_sensor_kernel<<<NE / EB, 256, smem_bytes>>>(   // 625 CTAs
        de, mask, W1, b1, W2, b2, W3, b3, out);
}